// round 2
// baseline (speedup 1.0000x reference)
#include <cuda_runtime.h>
#include <math.h>

// Shapes: x (32,256,32,32) f32, weight (256,256,3,3) f32, bias (256) f32
// Output: y (32,256,32,32) f32 followed by scalar L.
#define NB_DIM 2304          // 9*256
#define Y_ELEMS (32*256*32*32)

__device__ float  d_wt[9 * 256 * 256];      // wt[t][c][p] = w[p][c][t]
__device__ float  d_Nb[NB_DIM * NB_DIM];    // Nb = A A^T, A[t*256+c][p] = wt
__device__ float  d_S[81 * 256];            // S[t*9+t'][p]
__device__ float  d_T[81 * 256];            // T[t*9+t'][c]
__device__ float  d_F[81 * 81];             // Frobenius products of Nb blocks
__device__ double d_acc[3];                 // rowsum, colsum, diag4

// ---------------- init accumulators ----------------
__global__ void k_init() {
    int i = blockIdx.x * blockDim.x + threadIdx.x;
    if (i < 81 * 81) d_F[i] = 0.f;
    if (i < 3) d_acc[i] = 0.0;
}

// ---------------- repack weight: wt[t][c][p] = w[p][c][t] ----------------
__global__ void k_repack(const float* __restrict__ w) {
    int idx = blockIdx.x * blockDim.x + threadIdx.x;
    if (idx >= 256 * 2304) return;
    int p = idx / 2304;
    int r = idx - p * 2304;
    int c = r / 9, t = r - c * 9;
    d_wt[(t * 256 + c) * 256 + p] = w[idx];
}

// ---------------- direct circular conv (y) ----------------
// y[b,co,i,j] = bias[co] + sum_{ci,a,b'} w[co,ci,a,b'] x[b,ci,(i+a-1)%32,(j+b'-1)%32]
__global__ __launch_bounds__(256, 2) void k_conv(const float* __restrict__ x,
                                                 const float* __restrict__ w,
                                                 const float* __restrict__ bias,
                                                 float* __restrict__ y) {
    __shared__ float xs[4][34][36];
    __shared__ float ws[16][4][9];
    int b   = blockIdx.x;
    int cob = blockIdx.y * 16;
    int tid = threadIdx.x;
    int tj  = tid & 31;
    int tr  = (tid >> 5) * 4;   // output rows tr..tr+3

    float acc[16][4];
#pragma unroll
    for (int i = 0; i < 16; i++)
#pragma unroll
        for (int k = 0; k < 4; k++) acc[i][k] = 0.f;

    const float* xb = x + (size_t)b * 256 * 1024;

    for (int c0 = 0; c0 < 256; c0 += 4) {
        __syncthreads();
        for (int idx = tid; idx < 4 * 34 * 34; idx += 256) {
            int cc  = idx / 1156;
            int rem = idx - cc * 1156;
            int r   = rem / 34, col = rem - r * 34;
            xs[cc][r][col] = xb[(c0 + cc) * 1024 + (((r + 31) & 31) << 5) + ((col + 31) & 31)];
        }
        for (int idx = tid; idx < 16 * 4 * 9; idx += 256) {
            int co  = idx / 36;
            int rem = idx - co * 36;
            int cc  = rem / 9, t = rem - cc * 9;
            ws[co][cc][t] = w[((cob + co) * 256 + c0 + cc) * 9 + t];
        }
        __syncthreads();
#pragma unroll 1
        for (int cc = 0; cc < 4; cc++) {
            float xv[6][3];
#pragma unroll
            for (int rr = 0; rr < 6; rr++)
#pragma unroll
                for (int dc = 0; dc < 3; dc++) xv[rr][dc] = xs[cc][tr + rr][tj + dc];
#pragma unroll
            for (int co = 0; co < 16; co++) {
                float w0 = ws[co][cc][0], w1 = ws[co][cc][1], w2 = ws[co][cc][2];
                float w3 = ws[co][cc][3], w4 = ws[co][cc][4], w5 = ws[co][cc][5];
                float w6 = ws[co][cc][6], w7 = ws[co][cc][7], w8 = ws[co][cc][8];
#pragma unroll
                for (int k = 0; k < 4; k++) {
                    float s = acc[co][k];
                    s += w0 * xv[k][0]     + w1 * xv[k][1]     + w2 * xv[k][2];
                    s += w3 * xv[k + 1][0] + w4 * xv[k + 1][1] + w5 * xv[k + 1][2];
                    s += w6 * xv[k + 2][0] + w7 * xv[k + 2][1] + w8 * xv[k + 2][2];
                    acc[co][k] = s;
                }
            }
        }
    }
#pragma unroll
    for (int co = 0; co < 16; co++) {
        float bv = bias[cob + co];
#pragma unroll
        for (int k = 0; k < 4; k++)
            y[(((size_t)b * 256 + cob + co) * 32 + tr + k) * 32 + tj] = acc[co][k] + bv;
    }
}

// ---------------- S[t*9+t'][p] = sum_c w_t[p,c] w_t'[p,c] ----------------
__global__ void k_S(const float* __restrict__ w) {
    __shared__ float sh[81];
    int p = blockIdx.x, tid = threadIdx.x;  // tid = c
    if (tid < 81) sh[tid] = 0.f;
    __syncthreads();
    float wv[9];
#pragma unroll
    for (int t = 0; t < 9; t++) wv[t] = w[(p * 256 + tid) * 9 + t];
#pragma unroll
    for (int t = 0; t < 9; t++)
#pragma unroll
        for (int t2 = t; t2 < 9; t2++) {
            float pr = wv[t] * wv[t2];
#pragma unroll
            for (int o = 16; o; o >>= 1) pr += __shfl_xor_sync(0xffffffffu, pr, o);
            if ((tid & 31) == 0) atomicAdd(&sh[t * 9 + t2], pr);
        }
    __syncthreads();
    if (tid < 81) {
        int t = tid / 9, t2 = tid - t * 9;
        d_S[tid * 256 + p] = (t2 >= t) ? sh[t * 9 + t2] : sh[t2 * 9 + t];
    }
}

// ---------------- T[t*9+t'][c] = sum_p w_t[p,c] w_t'[p,c] ----------------
__global__ void k_T() {
    __shared__ float sh[81];
    int c = blockIdx.x, tid = threadIdx.x;  // tid = p
    if (tid < 81) sh[tid] = 0.f;
    __syncthreads();
    float wv[9];
#pragma unroll
    for (int t = 0; t < 9; t++) wv[t] = d_wt[(t * 256 + c) * 256 + tid];
#pragma unroll
    for (int t = 0; t < 9; t++)
#pragma unroll
        for (int t2 = t; t2 < 9; t2++) {
            float pr = wv[t] * wv[t2];
#pragma unroll
            for (int o = 16; o; o >>= 1) pr += __shfl_xor_sync(0xffffffffu, pr, o);
            if ((tid & 31) == 0) atomicAdd(&sh[t * 9 + t2], pr);
        }
    __syncthreads();
    if (tid < 81) {
        int t = tid / 9, t2 = tid - t * 9;
        d_T[tid * 256 + c] = (t2 >= t) ? sh[t * 9 + t2] : sh[t2 * 9 + t];
    }
}

// ---------------- per-bin row/col norms + diag^2 accumulation ----------------
__global__ void k_rowcol() {
    __shared__ float cosv[81];
    __shared__ double red[3][8];
    int bin = blockIdx.x;
    int u = bin / 17, v = bin - u * 17;
    int tid = threadIdx.x;
    if (tid < 81) {
        int t = tid / 9, t2 = tid - t * 9;
        int da = t / 3 - t2 / 3;
        int db = (t % 3) - (t2 % 3);
        cosv[tid] = cospif((float)(u * da + v * db) / 16.0f);  // cos(2*pi*m/32)
    }
    __syncthreads();
    float rn2 = 0.f, cn2 = 0.f;
#pragma unroll
    for (int q = 0; q < 81; q++) {
        float cq = cosv[q];
        rn2 += cq * d_S[q * 256 + tid];
        cn2 += cq * d_T[q * 256 + tid];
    }
    float rdev = sqrtf(fmaxf(rn2, 0.f)) - 1.f;
    float cdev = sqrtf(fmaxf(cn2, 0.f)) - 1.f;
    double v0 = (double)rdev * (double)rdev;
    double v1 = (double)cdev * (double)cdev;
    double v2 = (double)rn2 * (double)rn2;
#pragma unroll
    for (int o = 16; o; o >>= 1) {
        v0 += __shfl_xor_sync(0xffffffffu, v0, o);
        v1 += __shfl_xor_sync(0xffffffffu, v1, o);
        v2 += __shfl_xor_sync(0xffffffffu, v2, o);
    }
    int wid = tid >> 5, lane = tid & 31;
    if (lane == 0) { red[0][wid] = v0; red[1][wid] = v1; red[2][wid] = v2; }
    __syncthreads();
    if (tid == 0) {
        double s0 = 0, s1 = 0, s2 = 0;
        for (int i = 0; i < 8; i++) { s0 += red[0][i]; s1 += red[1][i]; s2 += red[2][i]; }
        atomicAdd(&d_acc[0], s0);
        atomicAdd(&d_acc[1], s1);
        atomicAdd(&d_acc[2], s2);
    }
}

// ---------------- Nb = A A^T, A = d_wt viewed as [2304][256] ----------------
__global__ __launch_bounds__(256) void k_nb() {
    __shared__ float As[16][65];
    __shared__ float Bs[16][65];
    int rt = blockIdx.y * 64, ct = blockIdx.x * 64;
    int tid = threadIdx.x;
    int tx = tid & 15, ty = tid >> 4;
    int lm = tid >> 2;            // 0..63
    int lk = (tid & 3) * 4;       // 0,4,8,12
    float acc[4][4];
#pragma unroll
    for (int i = 0; i < 4; i++)
#pragma unroll
        for (int j = 0; j < 4; j++) acc[i][j] = 0.f;

    for (int k0 = 0; k0 < 256; k0 += 16) {
        float4 a4 = *(const float4*)&d_wt[(rt + lm) * 256 + k0 + lk];
        float4 b4 = *(const float4*)&d_wt[(ct + lm) * 256 + k0 + lk];
        __syncthreads();
        As[lk + 0][lm] = a4.x; As[lk + 1][lm] = a4.y; As[lk + 2][lm] = a4.z; As[lk + 3][lm] = a4.w;
        Bs[lk + 0][lm] = b4.x; Bs[lk + 1][lm] = b4.y; Bs[lk + 2][lm] = b4.z; Bs[lk + 3][lm] = b4.w;
        __syncthreads();
#pragma unroll
        for (int kk = 0; kk < 16; kk++) {
            float av[4], bv[4];
#pragma unroll
            for (int q = 0; q < 4; q++) { av[q] = As[kk][ty * 4 + q]; bv[q] = Bs[kk][tx * 4 + q]; }
#pragma unroll
            for (int i = 0; i < 4; i++)
#pragma unroll
                for (int j = 0; j < 4; j++) acc[i][j] += av[i] * bv[j];
        }
    }
#pragma unroll
    for (int i = 0; i < 4; i++)
#pragma unroll
        for (int j = 0; j < 4; j++)
            d_Nb[(size_t)(rt + ty * 4 + i) * NB_DIM + ct + tx * 4 + j] = acc[i][j];
}

// ---------------- F[(u,v),(u',v')] = <Nb block uv, Nb block u'v'>_F (split-K) ----------------
__global__ __launch_bounds__(256) void k_F() {
    __shared__ float Vb[81][65];
    int tid = threadIdx.x;
    int t1 = tid, t2 = tid + 256;   // tiles of 4x4 over 21x21 = 441 tile grid
    float a1[16], a2[16];
#pragma unroll
    for (int q = 0; q < 16; q++) { a1[q] = 0.f; a2[q] = 0.f; }
    int i1 = (t1 / 21) * 4, j1 = (t1 % 21) * 4;
    int i2 = (t2 / 21) * 4, j2 = (t2 % 21) * 4;

    for (int chunk = blockIdx.x; chunk < 1024; chunk += gridDim.x) {
        __syncthreads();
        int k0  = chunk * 64;
        int c   = k0 >> 8;
        int cp0 = k0 & 255;
        for (int idx = tid; idx < 81 * 64; idx += 256) {
            int r = idx >> 6, kk = idx & 63;
            int uu = r / 9, vv = r - uu * 9;
            Vb[r][kk] = d_Nb[(size_t)(uu * 256 + c) * NB_DIM + vv * 256 + cp0 + kk];
        }
        __syncthreads();
        for (int kk = 0; kk < 64; kk++) {
            float av[4], bv[4];
#pragma unroll
            for (int q = 0; q < 4; q++) {
                av[q] = (i1 + q < 81) ? Vb[i1 + q][kk] : 0.f;
                bv[q] = (j1 + q < 81) ? Vb[j1 + q][kk] : 0.f;
            }
#pragma unroll
            for (int qi = 0; qi < 4; qi++)
#pragma unroll
                for (int qj = 0; qj < 4; qj++) a1[qi * 4 + qj] += av[qi] * bv[qj];
            if (t2 < 441) {
#pragma unroll
                for (int q = 0; q < 4; q++) {
                    av[q] = (i2 + q < 81) ? Vb[i2 + q][kk] : 0.f;
                    bv[q] = (j2 + q < 81) ? Vb[j2 + q][kk] : 0.f;
                }
#pragma unroll
                for (int qi = 0; qi < 4; qi++)
#pragma unroll
                    for (int qj = 0; qj < 4; qj++) a2[qi * 4 + qj] += av[qi] * bv[qj];
            }
        }
    }
#pragma unroll
    for (int qi = 0; qi < 4; qi++)
#pragma unroll
        for (int qj = 0; qj < 4; qj++) {
            if (i1 + qi < 81 && j1 + qj < 81) atomicAdd(&d_F[(i1 + qi) * 81 + j1 + qj], a1[qi * 4 + qj]);
            if (t2 < 441 && i2 + qi < 81 && j2 + qj < 81) atomicAdd(&d_F[(i2 + qi) * 81 + j2 + qj], a2[qi * 4 + qj]);
        }
}

// ---------------- final: assemble L ----------------
__global__ void k_final(float* __restrict__ out, long long lpos) {
    __shared__ double Vt[5];
    __shared__ double red[8];
    int tid = threadIdx.x;
    if (tid < 5) {
        double s = 0.0;
        for (int v = 0; v <= 16; v++) s += cos(M_PI * (double)tid * (double)v / 16.0);
        Vt[tid] = s;
    }
    __syncthreads();
    double tf = 0.0;
    for (int idx = tid; idx < 6561; idx += blockDim.x) {
        int t  = idx / 729;
        int tp = (idx / 81) % 9;
        int s  = (idx / 9) % 9;
        int sp = idx % 9;
        if ((t / 3 - tp / 3) != (s / 3 - sp / 3)) continue;
        int db = ((t % 3) - (tp % 3)) - ((s % 3) - (sp % 3));
        if (db < 0) db = -db;
        tf += 32.0 * Vt[db] * (double)d_F[(t * 9 + s) * 81 + (tp * 9 + sp)];
    }
#pragma unroll
    for (int o = 16; o; o >>= 1) tf += __shfl_xor_sync(0xffffffffu, tf, o);
    if ((tid & 31) == 0) red[tid >> 5] = tf;
    __syncthreads();
    if (tid == 0) {
        double total = 0.0;
        for (int i = 0; i < 8; i++) total += red[i];
        double count   = 544.0 * (256.0 * 255.0 * 0.5);
        double Ang     = (total - d_acc[2]) * 0.5 / count;
        double RowLoss = d_acc[0] / (544.0 * 256.0);
        double ColLoss = d_acc[1] / (544.0 * 256.0);
        double L = 256.0 * ColLoss + 256.0 * RowLoss + Ang;
        if (lpos >= 0) out[lpos] = (float)L;
    }
}

extern "C" void kernel_launch(void* const* d_in, const int* in_sizes, int n_in,
                              void* d_out, int out_size) {
    const float* x    = (const float*)d_in[0];
    const float* w    = (const float*)d_in[1];
    const float* bias = (const float*)d_in[2];
    float* out = (float*)d_out;

    k_init<<<26, 256>>>();
    k_repack<<<(256 * 2304 + 255) / 256, 256>>>(w);
    k_conv<<<dim3(32, 16), 256>>>(x, w, bias, out);
    k_S<<<256, 256>>>(w);
    k_T<<<256, 256>>>();
    k_rowcol<<<544, 256>>>();
    k_nb<<<dim3(36, 36), 256>>>();
    k_F<<<256, 256>>>();
    long long lpos = (out_size > Y_ELEMS) ? (long long)out_size - 1 : -1;
    k_final<<<1, 256>>>(out, lpos);
    (void)in_sizes; (void)n_in;
}

// round 4
// speedup vs baseline: 1.0001x; 1.0001x over previous
#include <cuda_runtime.h>
#include <math.h>

// Shapes: x (32,256,32,32) f32, weight (256,256,3,3) f32, bias (256) f32
// Output: y (32,256,32,32) f32 followed by scalar L.
#define NB_DIM 2304          // 9*256
#define Y_ELEMS (32*256*32*32)

__device__ float  d_wt[9 * 256 * 256];      // wt[t][c][p] = w[p][c][t]
__device__ float  d_Nb[NB_DIM * NB_DIM];    // Nb = A A^T, A[t*256+c][p] = wt
__device__ float  d_S[81 * 256];            // S[t*9+t'][p]
__device__ float  d_T[81 * 256];            // T[t*9+t'][c]
__device__ float  d_F[81 * 81];             // Frobenius products of Nb blocks
__device__ double d_acc[3];                 // rowsum, colsum, diag4

// ---------------- init accumulators ----------------
__global__ void k_init() {
    int i = blockIdx.x * blockDim.x + threadIdx.x;
    if (i < 81 * 81) d_F[i] = 0.f;
    if (i < 3) d_acc[i] = 0.0;
}

// ---------------- repack weight: wt[t][c][p] = w[p][c][t] ----------------
__global__ void k_repack(const float* __restrict__ w) {
    int idx = blockIdx.x * blockDim.x + threadIdx.x;
    if (idx >= 256 * 2304) return;
    int p = idx / 2304;
    int r = idx - p * 2304;
    int c = r / 9, t = r - c * 9;
    d_wt[(t * 256 + c) * 256 + p] = w[idx];
}

// ---------------- direct circular conv (y) ----------------
// y[b,co,i,j] = bias[co] + sum_{ci,a,b'} w[co,ci,a,b'] x[b,ci,(i+a-1)%32,(j+b'-1)%32]
__global__ __launch_bounds__(256, 2) void k_conv(const float* __restrict__ x,
                                                 const float* __restrict__ w,
                                                 const float* __restrict__ bias,
                                                 float* __restrict__ y) {
    __shared__ float xs[4][34][36];
    __shared__ float ws[16][4][9];
    int b   = blockIdx.x;
    int cob = blockIdx.y * 16;
    int tid = threadIdx.x;
    int tj  = tid & 31;
    int tr  = (tid >> 5) * 4;   // output rows tr..tr+3

    float acc[16][4];
#pragma unroll
    for (int i = 0; i < 16; i++)
#pragma unroll
        for (int k = 0; k < 4; k++) acc[i][k] = 0.f;

    const float* xb = x + (size_t)b * 256 * 1024;

    for (int c0 = 0; c0 < 256; c0 += 4) {
        __syncthreads();
        for (int idx = tid; idx < 4 * 34 * 34; idx += 256) {
            int cc  = idx / 1156;
            int rem = idx - cc * 1156;
            int r   = rem / 34, col = rem - r * 34;
            xs[cc][r][col] = xb[(c0 + cc) * 1024 + (((r + 31) & 31) << 5) + ((col + 31) & 31)];
        }
        for (int idx = tid; idx < 16 * 4 * 9; idx += 256) {
            int co  = idx / 36;
            int rem = idx - co * 36;
            int cc  = rem / 9, t = rem - cc * 9;
            ws[co][cc][t] = w[((cob + co) * 256 + c0 + cc) * 9 + t];
        }
        __syncthreads();
#pragma unroll 1
        for (int cc = 0; cc < 4; cc++) {
            float xv[6][3];
#pragma unroll
            for (int rr = 0; rr < 6; rr++)
#pragma unroll
                for (int dc = 0; dc < 3; dc++) xv[rr][dc] = xs[cc][tr + rr][tj + dc];
#pragma unroll
            for (int co = 0; co < 16; co++) {
                float w0 = ws[co][cc][0], w1 = ws[co][cc][1], w2 = ws[co][cc][2];
                float w3 = ws[co][cc][3], w4 = ws[co][cc][4], w5 = ws[co][cc][5];
                float w6 = ws[co][cc][6], w7 = ws[co][cc][7], w8 = ws[co][cc][8];
#pragma unroll
                for (int k = 0; k < 4; k++) {
                    float s = acc[co][k];
                    s += w0 * xv[k][0]     + w1 * xv[k][1]     + w2 * xv[k][2];
                    s += w3 * xv[k + 1][0] + w4 * xv[k + 1][1] + w5 * xv[k + 1][2];
                    s += w6 * xv[k + 2][0] + w7 * xv[k + 2][1] + w8 * xv[k + 2][2];
                    acc[co][k] = s;
                }
            }
        }
    }
#pragma unroll
    for (int co = 0; co < 16; co++) {
        float bv = bias[cob + co];
#pragma unroll
        for (int k = 0; k < 4; k++)
            y[(((size_t)b * 256 + cob + co) * 32 + tr + k) * 32 + tj] = acc[co][k] + bv;
    }
}

// ---------------- S[t*9+t'][p] = sum_c w_t[p,c] w_t'[p,c] ----------------
__global__ void k_S(const float* __restrict__ w) {
    __shared__ float sh[81];
    int p = blockIdx.x, tid = threadIdx.x;  // tid = c
    if (tid < 81) sh[tid] = 0.f;
    __syncthreads();
    float wv[9];
#pragma unroll
    for (int t = 0; t < 9; t++) wv[t] = w[(p * 256 + tid) * 9 + t];
#pragma unroll
    for (int t = 0; t < 9; t++)
#pragma unroll
        for (int t2 = t; t2 < 9; t2++) {
            float pr = wv[t] * wv[t2];
#pragma unroll
            for (int o = 16; o; o >>= 1) pr += __shfl_xor_sync(0xffffffffu, pr, o);
            if ((tid & 31) == 0) atomicAdd(&sh[t * 9 + t2], pr);
        }
    __syncthreads();
    if (tid < 81) {
        int t = tid / 9, t2 = tid - t * 9;
        d_S[tid * 256 + p] = (t2 >= t) ? sh[t * 9 + t2] : sh[t2 * 9 + t];
    }
}

// ---------------- T[t*9+t'][c] = sum_p w_t[p,c] w_t'[p,c] ----------------
__global__ void k_T() {
    __shared__ float sh[81];
    int c = blockIdx.x, tid = threadIdx.x;  // tid = p
    if (tid < 81) sh[tid] = 0.f;
    __syncthreads();
    float wv[9];
#pragma unroll
    for (int t = 0; t < 9; t++) wv[t] = d_wt[(t * 256 + c) * 256 + tid];
#pragma unroll
    for (int t = 0; t < 9; t++)
#pragma unroll
        for (int t2 = t; t2 < 9; t2++) {
            float pr = wv[t] * wv[t2];
#pragma unroll
            for (int o = 16; o; o >>= 1) pr += __shfl_xor_sync(0xffffffffu, pr, o);
            if ((tid & 31) == 0) atomicAdd(&sh[t * 9 + t2], pr);
        }
    __syncthreads();
    if (tid < 81) {
        int t = tid / 9, t2 = tid - t * 9;
        d_T[tid * 256 + c] = (t2 >= t) ? sh[t * 9 + t2] : sh[t2 * 9 + t];
    }
}

// ---------------- per-bin row/col norms + diag^2 accumulation ----------------
__global__ void k_rowcol() {
    __shared__ float cosv[81];
    __shared__ double red[3][8];
    int bin = blockIdx.x;
    int u = bin / 17, v = bin - u * 17;
    int tid = threadIdx.x;
    if (tid < 81) {
        int t = tid / 9, t2 = tid - t * 9;
        int da = t / 3 - t2 / 3;
        int db = (t % 3) - (t2 % 3);
        cosv[tid] = cospif((float)(u * da + v * db) / 16.0f);  // cos(2*pi*m/32)
    }
    __syncthreads();
    float rn2 = 0.f, cn2 = 0.f;
#pragma unroll
    for (int q = 0; q < 81; q++) {
        float cq = cosv[q];
        rn2 += cq * d_S[q * 256 + tid];
        cn2 += cq * d_T[q * 256 + tid];
    }
    float rdev = sqrtf(fmaxf(rn2, 0.f)) - 1.f;
    float cdev = sqrtf(fmaxf(cn2, 0.f)) - 1.f;
    double v0 = (double)rdev * (double)rdev;
    double v1 = (double)cdev * (double)cdev;
    double v2 = (double)rn2 * (double)rn2;
#pragma unroll
    for (int o = 16; o; o >>= 1) {
        v0 += __shfl_xor_sync(0xffffffffu, v0, o);
        v1 += __shfl_xor_sync(0xffffffffu, v1, o);
        v2 += __shfl_xor_sync(0xffffffffu, v2, o);
    }
    int wid = tid >> 5, lane = tid & 31;
    if (lane == 0) { red[0][wid] = v0; red[1][wid] = v1; red[2][wid] = v2; }
    __syncthreads();
    if (tid == 0) {
        double s0 = 0, s1 = 0, s2 = 0;
        for (int i = 0; i < 8; i++) { s0 += red[0][i]; s1 += red[1][i]; s2 += red[2][i]; }
        atomicAdd(&d_acc[0], s0);
        atomicAdd(&d_acc[1], s1);
        atomicAdd(&d_acc[2], s2);
    }
}

// ---------------- Nb = A A^T, A = d_wt viewed as [2304][256] ----------------
__global__ __launch_bounds__(256) void k_nb() {
    __shared__ float As[16][65];
    __shared__ float Bs[16][65];
    int rt = blockIdx.y * 64, ct = blockIdx.x * 64;
    int tid = threadIdx.x;
    int tx = tid & 15, ty = tid >> 4;
    int lm = tid >> 2;            // 0..63
    int lk = (tid & 3) * 4;       // 0,4,8,12
    float acc[4][4];
#pragma unroll
    for (int i = 0; i < 4; i++)
#pragma unroll
        for (int j = 0; j < 4; j++) acc[i][j] = 0.f;

    for (int k0 = 0; k0 < 256; k0 += 16) {
        float4 a4 = *(const float4*)&d_wt[(rt + lm) * 256 + k0 + lk];
        float4 b4 = *(const float4*)&d_wt[(ct + lm) * 256 + k0 + lk];
        __syncthreads();
        As[lk + 0][lm] = a4.x; As[lk + 1][lm] = a4.y; As[lk + 2][lm] = a4.z; As[lk + 3][lm] = a4.w;
        Bs[lk + 0][lm] = b4.x; Bs[lk + 1][lm] = b4.y; Bs[lk + 2][lm] = b4.z; Bs[lk + 3][lm] = b4.w;
        __syncthreads();
#pragma unroll
        for (int kk = 0; kk < 16; kk++) {
            float av[4], bv[4];
#pragma unroll
            for (int q = 0; q < 4; q++) { av[q] = As[kk][ty * 4 + q]; bv[q] = Bs[kk][tx * 4 + q]; }
#pragma unroll
            for (int i = 0; i < 4; i++)
#pragma unroll
                for (int j = 0; j < 4; j++) acc[i][j] += av[i] * bv[j];
        }
    }
#pragma unroll
    for (int i = 0; i < 4; i++)
#pragma unroll
        for (int j = 0; j < 4; j++)
            d_Nb[(size_t)(rt + ty * 4 + i) * NB_DIM + ct + tx * 4 + j] = acc[i][j];
}

// ---------------- F[(u,v),(u',v')] = <Nb block uv, Nb block u'v'>_F (split-K) ----------------
__global__ __launch_bounds__(256) void k_F() {
    __shared__ float Vb[81][65];
    int tid = threadIdx.x;
    int t1 = tid, t2 = tid + 256;   // tiles of 4x4 over 21x21 = 441 tile grid
    float a1[16], a2[16];
#pragma unroll
    for (int q = 0; q < 16; q++) { a1[q] = 0.f; a2[q] = 0.f; }
    int i1 = (t1 / 21) * 4, j1 = (t1 % 21) * 4;
    int i2 = (t2 / 21) * 4, j2 = (t2 % 21) * 4;

    for (int chunk = blockIdx.x; chunk < 1024; chunk += gridDim.x) {
        __syncthreads();
        int k0  = chunk * 64;
        int c   = k0 >> 8;
        int cp0 = k0 & 255;
        for (int idx = tid; idx < 81 * 64; idx += 256) {
            int r = idx >> 6, kk = idx & 63;
            int uu = r / 9, vv = r - uu * 9;
            Vb[r][kk] = d_Nb[(size_t)(uu * 256 + c) * NB_DIM + vv * 256 + cp0 + kk];
        }
        __syncthreads();
        for (int kk = 0; kk < 64; kk++) {
            float av[4], bv[4];
#pragma unroll
            for (int q = 0; q < 4; q++) {
                av[q] = (i1 + q < 81) ? Vb[i1 + q][kk] : 0.f;
                bv[q] = (j1 + q < 81) ? Vb[j1 + q][kk] : 0.f;
            }
#pragma unroll
            for (int qi = 0; qi < 4; qi++)
#pragma unroll
                for (int qj = 0; qj < 4; qj++) a1[qi * 4 + qj] += av[qi] * bv[qj];
            if (t2 < 441) {
#pragma unroll
                for (int q = 0; q < 4; q++) {
                    av[q] = (i2 + q < 81) ? Vb[i2 + q][kk] : 0.f;
                    bv[q] = (j2 + q < 81) ? Vb[j2 + q][kk] : 0.f;
                }
#pragma unroll
                for (int qi = 0; qi < 4; qi++)
#pragma unroll
                    for (int qj = 0; qj < 4; qj++) a2[qi * 4 + qj] += av[qi] * bv[qj];
            }
        }
    }
#pragma unroll
    for (int qi = 0; qi < 4; qi++)
#pragma unroll
        for (int qj = 0; qj < 4; qj++) {
            if (i1 + qi < 81 && j1 + qj < 81) atomicAdd(&d_F[(i1 + qi) * 81 + j1 + qj], a1[qi * 4 + qj]);
            if (t2 < 441 && i2 + qi < 81 && j2 + qj < 81) atomicAdd(&d_F[(i2 + qi) * 81 + j2 + qj], a2[qi * 4 + qj]);
        }
}

// ---------------- final: assemble L ----------------
__global__ void k_final(float* __restrict__ out, long long lpos) {
    __shared__ double Vt[5];
    __shared__ double red[8];
    int tid = threadIdx.x;
    if (tid < 5) {
        double s = 0.0;
        for (int v = 0; v <= 16; v++) s += cos(M_PI * (double)tid * (double)v / 16.0);
        Vt[tid] = s;
    }
    __syncthreads();
    double tf = 0.0;
    for (int idx = tid; idx < 6561; idx += blockDim.x) {
        int t  = idx / 729;
        int tp = (idx / 81) % 9;
        int s  = (idx / 9) % 9;
        int sp = idx % 9;
        if ((t / 3 - tp / 3) != (s / 3 - sp / 3)) continue;
        int db = ((t % 3) - (tp % 3)) - ((s % 3) - (sp % 3));
        if (db < 0) db = -db;
        tf += 32.0 * Vt[db] * (double)d_F[(t * 9 + s) * 81 + (tp * 9 + sp)];
    }
#pragma unroll
    for (int o = 16; o; o >>= 1) tf += __shfl_xor_sync(0xffffffffu, tf, o);
    if ((tid & 31) == 0) red[tid >> 5] = tf;
    __syncthreads();
    if (tid == 0) {
        double total = 0.0;
        for (int i = 0; i < 8; i++) total += red[i];
        double count   = 544.0 * (256.0 * 255.0 * 0.5);
        double Ang     = (total - d_acc[2]) * 0.5 / count;
        double RowLoss = d_acc[0] / (544.0 * 256.0);
        double ColLoss = d_acc[1] / (544.0 * 256.0);
        double L = 256.0 * ColLoss + 256.0 * RowLoss + Ang;
        if (lpos >= 0) out[lpos] = (float)L;
    }
}

extern "C" void kernel_launch(void* const* d_in, const int* in_sizes, int n_in,
                              void* d_out, int out_size) {
    const float* x    = (const float*)d_in[0];
    const float* w    = (const float*)d_in[1];
    const float* bias = (const float*)d_in[2];
    float* out = (float*)d_out;

    k_init<<<26, 256>>>();
    k_repack<<<(256 * 2304 + 255) / 256, 256>>>(w);
    k_conv<<<dim3(32, 16), 256>>>(x, w, bias, out);
    k_S<<<256, 256>>>(w);
    k_T<<<256, 256>>>();
    k_rowcol<<<544, 256>>>();
    k_nb<<<dim3(36, 36), 256>>>();
    k_F<<<256, 256>>>();
    long long lpos = (out_size > Y_ELEMS) ? (long long)out_size - 1 : -1;
    k_final<<<1, 256>>>(out, lpos);
    (void)in_sizes; (void)n_in;
}

// round 8
// speedup vs baseline: 2.3249x; 2.3246x over previous
#include <cuda_runtime.h>
#include <cuda_bf16.h>
#include <math.h>
#include <stdint.h>

// x (32,256,32,32) f32, weight (256,256,3,3) f32, bias (256) f32
// out: y (32,256,32,32) f32 followed by scalar L.
#define NB_DIM 2304
#define Y_ELEMS (32*256*32*32)

__device__ float    d_wt[9 * 256 * 256];      // wt[t][c][p] = w[p][c][t]
__device__ float    d_Nb[NB_DIM * NB_DIM];
__device__ float    d_S[81 * 256];
__device__ float    d_T[81 * 256];
__device__ float    d_F[81 * 81];
__device__ double   d_acc[3];
__device__ uint32_t d_xt[32 * 34 * 34 * 256];   // padded x, packed (lo<<16)|hi bf16
__device__ uint32_t d_wB2[72 * 256 * 36];       // 72 stages [co 256][stride 36], packed bf16 pair

// ===== helpers =====
__device__ __forceinline__ uint32_t prmt32(uint32_t a, uint32_t b, uint32_t sel) {
    uint32_t d;
    asm("prmt.b32 %0, %1, %2, %3;" : "=r"(d) : "r"(a), "r"(b), "r"(sel));
    return d;
}
__device__ __forceinline__ void mma_bf16(float* d, const uint32_t* a, uint32_t b0, uint32_t b1) {
    asm volatile(
        "mma.sync.aligned.m16n8k16.row.col.f32.bf16.bf16.f32 "
        "{%0,%1,%2,%3},{%4,%5,%6,%7},{%8,%9},{%0,%1,%2,%3};"
        : "+f"(d[0]), "+f"(d[1]), "+f"(d[2]), "+f"(d[3])
        : "r"(a[0]), "r"(a[1]), "r"(a[2]), "r"(a[3]), "r"(b0), "r"(b1));
}
__device__ __forceinline__ uint32_t pack_hilo(float f) {
    __nv_bfloat16 h = __float2bfloat16(f);
    float fh = __bfloat162float(h);
    __nv_bfloat16 l = __float2bfloat16(f - fh);
    return ((uint32_t)__bfloat16_as_ushort(l) << 16) | (uint32_t)__bfloat16_as_ushort(h);
}
#define CP_ASYNC16(dst, src) \
    asm volatile("cp.async.cg.shared.global [%0], [%1], 16;" :: "r"(dst), "l"(src) : "memory")
#define CP_COMMIT() asm volatile("cp.async.commit_group;" ::: "memory")
#define CP_WAIT1()  asm volatile("cp.async.wait_group 1;" ::: "memory")

// ===== init =====
__global__ void k_init() {
    int i = blockIdx.x * blockDim.x + threadIdx.x;
    if (i < 81 * 81) d_F[i] = 0.f;
    if (i < 3) d_acc[i] = 0.0;
}

// ===== repack weight: wt[t][c][p] = w[p][c][t] =====
__global__ void k_repack(const float* __restrict__ w) {
    int idx = blockIdx.x * blockDim.x + threadIdx.x;
    if (idx >= 256 * 2304) return;
    int p = idx / 2304;
    int r = idx - p * 2304;
    int c = r / 9, t = r - c * 9;
    d_wt[(t * 256 + c) * 256 + p] = w[idx];
}

// ===== build d_xt: padded [b][hr34][hc34][ci256] packed bf16 hi/lo =====
__global__ void k_xt(const float* __restrict__ x) {
    __shared__ uint32_t s[34][256];
    int hr = blockIdx.x;     // 0..33
    int b  = blockIdx.y;     // 0..31
    int tid = threadIdx.x;
    int hsrc = (hr + 31) & 31;
    for (int idx = tid; idx < 8192; idx += 256) {
        int ci = idx >> 5, w = idx & 31;
        float f = x[(((size_t)b * 256 + ci) * 32 + hsrc) * 32 + w];
        s[w + 1][ci] = pack_hilo(f);
    }
    __syncthreads();
    if (tid < 256) { s[0][tid] = s[32][tid]; s[33][tid] = s[1][tid]; }
    __syncthreads();
    for (int idx = tid; idx < 34 * 256; idx += 256) {
        int hc = idx >> 8, ci = idx & 255;
        d_xt[(((size_t)b * 34 + hr) * 34 + hc) * 256 + ci] = s[hc][ci];
    }
}

// ===== pack W stages: stage s=chunk*9+tap : [co][ci32] packed, stride 36 =====
__global__ void k_wB2(const float* __restrict__ w) {
    int idx = blockIdx.x * 256 + threadIdx.x;
    if (idx >= 72 * 8192) return;
    int s = idx >> 13;
    int r = idx & 8191;
    int co = r >> 5, ci = r & 31;
    int chunk = s / 9, tap = s - chunk * 9;
    float v = w[(co * 256 + chunk * 32 + ci) * 9 + tap];
    d_wB2[(size_t)s * 9216 + co * 36 + ci] = pack_hilo(v);
}

// ===== mma.sync conv =====
// grid (32 b, 8 rowblock), 256 threads (8 warps: 2 M x 4 N)
// D[128 pix][256 co], K = 9 taps x 8 chunks x 32 ci
#define HALO_STRIDE 36
#define OFF_HALO   0
#define OFF_RING   29376                 // 204*36*4
#define RING_U32   9216                  // 256*36
#define RING_BYTES 36864
#define OFF_BIAS   139968                // 29376 + 3*36864
#define SMEM_BYTES 140992

__global__ __launch_bounds__(256, 1)
void k_conv_mma(const float* __restrict__ bias, float* __restrict__ y) {
    extern __shared__ uint32_t sm[];
    uint32_t* sHalo = sm;                              // [204][36]
    uint32_t* sRing = sm + OFF_RING / 4;               // 3 x [256][36]
    float*    sEpi  = (float*)sm;                      // [256][129] reuse
    float*    sBias = (float*)(sm + OFF_BIAS / 4);
    uint32_t sbase;
    asm("{ .reg .u64 t; cvta.to.shared.u64 t, %1; cvt.u32.u64 %0, t; }"
        : "=r"(sbase) : "l"((void*)sm));

    int tid  = threadIdx.x;
    int lane = tid & 31, warp = tid >> 5;
    int wm = warp >> 2, wn = warp & 3;     // 2 x 4
    int b = blockIdx.x, r0 = blockIdx.y * 4;

    sBias[tid] = bias[tid];

    float acc[4][8][4];
#pragma unroll
    for (int i = 0; i < 4; i++)
#pragma unroll
        for (int j = 0; j < 8; j++)
#pragma unroll
            for (int q = 0; q < 4; q++) acc[i][j][q] = 0.f;

    // prologue: W stages 0, 1
#pragma unroll
    for (int s0 = 0; s0 < 2; s0++) {
        const char* src = (const char*)d_wB2 + (size_t)s0 * RING_BYTES;
        uint32_t dst = sbase + OFF_RING + (uint32_t)s0 * RING_BYTES;
#pragma unroll
        for (int q = 0; q < 9; q++) {
            int off = (q * 256 + tid) * 16;
            CP_ASYNC16(dst + off, src + off);
        }
        CP_COMMIT();
    }

    int lr = lane >> 2;         // 0..7
    int lk = (lane & 3) * 2;    // 0,2,4,6

#pragma unroll 1
    for (int s = 0; s < 72; s++) {
        int chunk = s / 9;
        int tap = s - chunk * 9;
        int ta = tap / 3, tb = tap - ta * 3;

        if (tap == 0) {
            __syncthreads();     // old halo no longer read
            int ci0 = chunk * 32;
            for (int f = tid; f < 6528; f += 256) {
                int seg = f >> 5, ci = f & 31;
                int hr = seg / 34, hc = seg - hr * 34;
                sHalo[seg * HALO_STRIDE + ci] =
                    d_xt[(((size_t)b * 34 + r0 + hr) * 34 + hc) * 256 + ci0 + ci];
            }
        }

        CP_WAIT1();
        __syncthreads();

        // prefetch stage s+2
        if (s + 2 < 72) {
            const char* src = (const char*)d_wB2 + (size_t)(s + 2) * RING_BYTES;
            uint32_t dst = sbase + OFF_RING + (uint32_t)((s + 2) % 3) * RING_BYTES;
#pragma unroll
            for (int q = 0; q < 9; q++) {
                int off = (q * 256 + tid) * 16;
                CP_ASYNC16(dst + off, src + off);
            }
        }
        CP_COMMIT();

        const uint32_t* Bp = sRing + (s % 3) * RING_U32;

        // A base segments per m-frag (independent of k2)
        int segb[4];
#pragma unroll
        for (int mf = 0; mf < 4; mf++) {
            int m0 = wm * 64 + mf * 16 + lr;
            int pr = m0 >> 5, pc = m0 & 31;
            segb[mf] = ((pr + ta) * 34 + pc + tb) * HALO_STRIDE;
        }

#pragma unroll
        for (int k2 = 0; k2 < 32; k2 += 16) {
            int kb = k2 + lk;
            uint32_t Ah[4][4], Al[4][4];
#pragma unroll
            for (int mf = 0; mf < 4; mf++) {
                const uint32_t* base = sHalo + segb[mf] + kb;
                uint2 u00 = *(const uint2*)(base);
                uint2 u10 = *(const uint2*)(base + 8 * HALO_STRIDE);
                uint2 u01 = *(const uint2*)(base + 8);
                uint2 u11 = *(const uint2*)(base + 8 * HALO_STRIDE + 8);
                Ah[mf][0] = prmt32(u00.x, u00.y, 0x5410); Al[mf][0] = prmt32(u00.x, u00.y, 0x7632);
                Ah[mf][1] = prmt32(u10.x, u10.y, 0x5410); Al[mf][1] = prmt32(u10.x, u10.y, 0x7632);
                Ah[mf][2] = prmt32(u01.x, u01.y, 0x5410); Al[mf][2] = prmt32(u01.x, u01.y, 0x7632);
                Ah[mf][3] = prmt32(u11.x, u11.y, 0x5410); Al[mf][3] = prmt32(u11.x, u11.y, 0x7632);
            }
#pragma unroll
            for (int nf = 0; nf < 8; nf++) {
                int co = wn * 64 + nf * 8 + lr;
                const uint32_t* bb = Bp + co * 36 + kb;
                uint2 v0 = *(const uint2*)(bb);
                uint2 v1 = *(const uint2*)(bb + 8);
                uint32_t Bh0 = prmt32(v0.x, v0.y, 0x5410), Bl0 = prmt32(v0.x, v0.y, 0x7632);
                uint32_t Bh1 = prmt32(v1.x, v1.y, 0x5410), Bl1 = prmt32(v1.x, v1.y, 0x7632);
#pragma unroll
                for (int mf = 0; mf < 4; mf++) {
                    mma_bf16(acc[mf][nf], Ah[mf], Bh0, Bh1);   // xh*wh
                    mma_bf16(acc[mf][nf], Ah[mf], Bl0, Bl1);   // xh*wl
                    mma_bf16(acc[mf][nf], Al[mf], Bh0, Bh1);   // xl*wh
                }
            }
        }
    }

    // epilogue: transpose through smem, add bias, coalesced store
    __syncthreads();
#pragma unroll
    for (int mf = 0; mf < 4; mf++)
#pragma unroll
        for (int nf = 0; nf < 8; nf++) {
            int m0 = wm * 64 + mf * 16 + lr;
            int co = wn * 64 + nf * 8 + lk;
            sEpi[(co + 0) * 129 + m0]     = acc[mf][nf][0];
            sEpi[(co + 1) * 129 + m0]     = acc[mf][nf][1];
            sEpi[(co + 0) * 129 + m0 + 8] = acc[mf][nf][2];
            sEpi[(co + 1) * 129 + m0 + 8] = acc[mf][nf][3];
        }
    __syncthreads();
    for (int idx = tid; idx < 32768; idx += 256) {
        int co = idx >> 7, m = idx & 127;
        float v = sEpi[co * 129 + m] + sBias[co];
        int i = r0 + (m >> 5), j = m & 31;
        y[(((size_t)b * 256 + co) * 32 + i) * 32 + j] = v;
    }
}

// ===== S[t*9+t'][p] = sum_c w_t[p,c] w_t'[p,c] =====
__global__ void k_S(const float* __restrict__ w) {
    __shared__ float sh[81];
    int p = blockIdx.x, tid = threadIdx.x;
    if (tid < 81) sh[tid] = 0.f;
    __syncthreads();
    float wv[9];
#pragma unroll
    for (int t = 0; t < 9; t++) wv[t] = w[(p * 256 + tid) * 9 + t];
#pragma unroll
    for (int t = 0; t < 9; t++)
#pragma unroll
        for (int t2 = t; t2 < 9; t2++) {
            float pr = wv[t] * wv[t2];
#pragma unroll
            for (int o = 16; o; o >>= 1) pr += __shfl_xor_sync(0xffffffffu, pr, o);
            if ((tid & 31) == 0) atomicAdd(&sh[t * 9 + t2], pr);
        }
    __syncthreads();
    if (tid < 81) {
        int t = tid / 9, t2 = tid - t * 9;
        d_S[tid * 256 + p] = (t2 >= t) ? sh[t * 9 + t2] : sh[t2 * 9 + t];
    }
}

// ===== T[t*9+t'][c] = sum_p w_t[p,c] w_t'[p,c] =====
__global__ void k_T() {
    __shared__ float sh[81];
    int c = blockIdx.x, tid = threadIdx.x;
    if (tid < 81) sh[tid] = 0.f;
    __syncthreads();
    float wv[9];
#pragma unroll
    for (int t = 0; t < 9; t++) wv[t] = d_wt[(t * 256 + c) * 256 + tid];
#pragma unroll
    for (int t = 0; t < 9; t++)
#pragma unroll
        for (int t2 = t; t2 < 9; t2++) {
            float pr = wv[t] * wv[t2];
#pragma unroll
            for (int o = 16; o; o >>= 1) pr += __shfl_xor_sync(0xffffffffu, pr, o);
            if ((tid & 31) == 0) atomicAdd(&sh[t * 9 + t2], pr);
        }
    __syncthreads();
    if (tid < 81) {
        int t = tid / 9, t2 = tid - t * 9;
        d_T[tid * 256 + c] = (t2 >= t) ? sh[t * 9 + t2] : sh[t2 * 9 + t];
    }
}

// ===== per-bin row/col norms + diag^2 =====
__global__ void k_rowcol() {
    __shared__ float cosv[81];
    __shared__ double red[3][8];
    int bin = blockIdx.x;
    int u = bin / 17, v = bin - u * 17;
    int tid = threadIdx.x;
    if (tid < 81) {
        int t = tid / 9, t2 = tid - t * 9;
        int da = t / 3 - t2 / 3;
        int db = (t % 3) - (t2 % 3);
        cosv[tid] = cospif((float)(u * da + v * db) / 16.0f);
    }
    __syncthreads();
    float rn2 = 0.f, cn2 = 0.f;
#pragma unroll
    for (int q = 0; q < 81; q++) {
        float cq = cosv[q];
        rn2 += cq * d_S[q * 256 + tid];
        cn2 += cq * d_T[q * 256 + tid];
    }
    float rdev = sqrtf(fmaxf(rn2, 0.f)) - 1.f;
    float cdev = sqrtf(fmaxf(cn2, 0.f)) - 1.f;
    double v0 = (double)rdev * (double)rdev;
    double v1 = (double)cdev * (double)cdev;
    double v2 = (double)rn2 * (double)rn2;
#pragma unroll
    for (int o = 16; o; o >>= 1) {
        v0 += __shfl_xor_sync(0xffffffffu, v0, o);
        v1 += __shfl_xor_sync(0xffffffffu, v1, o);
        v2 += __shfl_xor_sync(0xffffffffu, v2, o);
    }
    int wid = tid >> 5, lane = tid & 31;
    if (lane == 0) { red[0][wid] = v0; red[1][wid] = v1; red[2][wid] = v2; }
    __syncthreads();
    if (tid == 0) {
        double s0 = 0, s1 = 0, s2 = 0;
        for (int i = 0; i < 8; i++) { s0 += red[0][i]; s1 += red[1][i]; s2 += red[2][i]; }
        atomicAdd(&d_acc[0], s0);
        atomicAdd(&d_acc[1], s1);
        atomicAdd(&d_acc[2], s2);
    }
}

// ===== Nb = A A^T =====
__global__ __launch_bounds__(256) void k_nb() {
    __shared__ float As[16][65];
    __shared__ float Bs[16][65];
    int rt = blockIdx.y * 64, ct = blockIdx.x * 64;
    int tid = threadIdx.x;
    int tx = tid & 15, ty = tid >> 4;
    int lm = tid >> 2;
    int lk = (tid & 3) * 4;
    float acc[4][4];
#pragma unroll
    for (int i = 0; i < 4; i++)
#pragma unroll
        for (int j = 0; j < 4; j++) acc[i][j] = 0.f;

    for (int k0 = 0; k0 < 256; k0 += 16) {
        float4 a4 = *(const float4*)&d_wt[(rt + lm) * 256 + k0 + lk];
        float4 b4 = *(const float4*)&d_wt[(ct + lm) * 256 + k0 + lk];
        __syncthreads();
        As[lk + 0][lm] = a4.x; As[lk + 1][lm] = a4.y; As[lk + 2][lm] = a4.z; As[lk + 3][lm] = a4.w;
        Bs[lk + 0][lm] = b4.x; Bs[lk + 1][lm] = b4.y; Bs[lk + 2][lm] = b4.z; Bs[lk + 3][lm] = b4.w;
        __syncthreads();
#pragma unroll
        for (int kk = 0; kk < 16; kk++) {
            float av[4], bv[4];
#pragma unroll
            for (int q = 0; q < 4; q++) { av[q] = As[kk][ty * 4 + q]; bv[q] = Bs[kk][tx * 4 + q]; }
#pragma unroll
            for (int i = 0; i < 4; i++)
#pragma unroll
                for (int j = 0; j < 4; j++) acc[i][j] += av[i] * bv[j];
        }
    }
#pragma unroll
    for (int i = 0; i < 4; i++)
#pragma unroll
        for (int j = 0; j < 4; j++)
            d_Nb[(size_t)(rt + ty * 4 + i) * NB_DIM + ct + tx * 4 + j] = acc[i][j];
}

// ===== F = Frobenius products of Nb blocks (split-K) =====
__global__ __launch_bounds__(256) void k_F() {
    __shared__ float Vb[81][65];
    int tid = threadIdx.x;
    int t1 = tid, t2 = tid + 256;
    float a1[16], a2[16];
#pragma unroll
    for (int q = 0; q < 16; q++) { a1[q] = 0.f; a2[q] = 0.f; }
    int i1 = (t1 / 21) * 4, j1 = (t1 % 21) * 4;
    int i2 = (t2 / 21) * 4, j2 = (t2 % 21) * 4;

    for (int chunk = blockIdx.x; chunk < 1024; chunk += gridDim.x) {
        __syncthreads();
        int k0  = chunk * 64;
        int c   = k0 >> 8;
        int cp0 = k0 & 255;
        for (int idx = tid; idx < 81 * 64; idx += 256) {
            int r = idx >> 6, kk = idx & 63;
            int uu = r / 9, vv = r - uu * 9;
            Vb[r][kk] = d_Nb[(size_t)(uu * 256 + c) * NB_DIM + vv * 256 + cp0 + kk];
        }
        __syncthreads();
        for (int kk = 0; kk < 64; kk++) {
            float av[4], bv[4];
#pragma unroll
            for (int q = 0; q < 4; q++) {
                av[q] = (i1 + q < 81) ? Vb[i1 + q][kk] : 0.f;
                bv[q] = (j1 + q < 81) ? Vb[j1 + q][kk] : 0.f;
            }
#pragma unroll
            for (int qi = 0; qi < 4; qi++)
#pragma unroll
                for (int qj = 0; qj < 4; qj++) a1[qi * 4 + qj] += av[qi] * bv[qj];
            if (t2 < 441) {
#pragma unroll
                for (int q = 0; q < 4; q++) {
                    av[q] = (i2 + q < 81) ? Vb[i2 + q][kk] : 0.f;
                    bv[q] = (j2 + q < 81) ? Vb[j2 + q][kk] : 0.f;
                }
#pragma unroll
                for (int qi = 0; qi < 4; qi++)
#pragma unroll
                    for (int qj = 0; qj < 4; qj++) a2[qi * 4 + qj] += av[qi] * bv[qj];
            }
        }
    }
#pragma unroll
    for (int qi = 0; qi < 4; qi++)
#pragma unroll
        for (int qj = 0; qj < 4; qj++) {
            if (i1 + qi < 81 && j1 + qj < 81) atomicAdd(&d_F[(i1 + qi) * 81 + j1 + qj], a1[qi * 4 + qj]);
            if (t2 < 441 && i2 + qi < 81 && j2 + qj < 81) atomicAdd(&d_F[(i2 + qi) * 81 + j2 + qj], a2[qi * 4 + qj]);
        }
}

// ===== final: assemble L =====
__global__ void k_final(float* __restrict__ out, long long lpos) {
    __shared__ double Vt[5];
    __shared__ double red[8];
    int tid = threadIdx.x;
    if (tid < 5) {
        double s = 0.0;
        for (int v = 0; v <= 16; v++) s += cos(M_PI * (double)tid * (double)v / 16.0);
        Vt[tid] = s;
    }
    __syncthreads();
    double tf = 0.0;
    for (int idx = tid; idx < 6561; idx += blockDim.x) {
        int t  = idx / 729;
        int tp = (idx / 81) % 9;
        int s  = (idx / 9) % 9;
        int sp = idx % 9;
        if ((t / 3 - tp / 3) != (s / 3 - sp / 3)) continue;
        int db = ((t % 3) - (tp % 3)) - ((s % 3) - (sp % 3));
        if (db < 0) db = -db;
        tf += 32.0 * Vt[db] * (double)d_F[(t * 9 + s) * 81 + (tp * 9 + sp)];
    }
#pragma unroll
    for (int o = 16; o; o >>= 1) tf += __shfl_xor_sync(0xffffffffu, tf, o);
    if ((tid & 31) == 0) red[tid >> 5] = tf;
    __syncthreads();
    if (tid == 0) {
        double total = 0.0;
        for (int i = 0; i < 8; i++) total += red[i];
        double count   = 544.0 * (256.0 * 255.0 * 0.5);
        double Ang     = (total - d_acc[2]) * 0.5 / count;
        double RowLoss = d_acc[0] / (544.0 * 256.0);
        double ColLoss = d_acc[1] / (544.0 * 256.0);
        double L = 256.0 * ColLoss + 256.0 * RowLoss + Ang;
        if (lpos >= 0) out[lpos] = (float)L;
    }
}

extern "C" void kernel_launch(void* const* d_in, const int* in_sizes, int n_in,
                              void* d_out, int out_size) {
    const float* x    = (const float*)d_in[0];
    const float* w    = (const float*)d_in[1];
    const float* bias = (const float*)d_in[2];
    float* out = (float*)d_out;

    cudaFuncSetAttribute(k_conv_mma, cudaFuncAttributeMaxDynamicSharedMemorySize, SMEM_BYTES);

    k_init<<<26, 256>>>();
    k_repack<<<(256 * 2304 + 255) / 256, 256>>>(w);
    k_xt<<<dim3(34, 32), 256>>>(x);
    k_wB2<<<2304, 256>>>(w);
    k_conv_mma<<<dim3(32, 8), 256, SMEM_BYTES>>>(bias, out);
    k_S<<<256, 256>>>(w);
    k_T<<<256, 256>>>();
    k_rowcol<<<544, 256>>>();
    k_nb<<<dim3(36, 36), 256>>>();
    k_F<<<256, 256>>>();
    long long lpos = (out_size > Y_ELEMS) ? (long long)out_size - 1 : -1;
    k_final<<<1, 256>>>(out, lpos);
    (void)in_sizes; (void)n_in;
}

// round 11
// speedup vs baseline: 3.1246x; 1.3440x over previous
#include <cuda_runtime.h>
#include <cuda_bf16.h>
#include <cuda_fp16.h>
#include <math.h>
#include <stdint.h>

// x (32,256,32,32) f32, weight (256,256,3,3) f32, bias (256) f32
// out: y (32,256,32,32) f32 followed by scalar L.
#define NB_DIM 2304
#define Y_ELEMS (32*256*32*32)

__device__ float    d_wt[9 * 256 * 256];      // wt[t][c][p] = w[p][c][t] (f32, for k_T)
__device__ uint32_t d_Ab[NB_DIM * 256];       // same layout, packed bf16 hi/lo (for k_nbm)
__device__ float    d_Nb[NB_DIM * NB_DIM];
__device__ float    d_S[81 * 256];
__device__ float    d_T[81 * 256];
__device__ float    d_F[81 * 81];
__device__ double   d_acc[3];
__device__ uint32_t d_xt[32 * 34 * 34 * 256]; // padded x, packed (xl<<16)|xh fp16
__device__ uint32_t d_wB2[72 * 5120];         // 72 stages [co 256][stride 20], fp16 ci-pairs

// ===== helpers =====
__device__ __forceinline__ uint32_t prmt32(uint32_t a, uint32_t b, uint32_t sel) {
    uint32_t d;
    asm("prmt.b32 %0, %1, %2, %3;" : "=r"(d) : "r"(a), "r"(b), "r"(sel));
    return d;
}
__device__ __forceinline__ void mma_bf16(float* d, const uint32_t* a, uint32_t b0, uint32_t b1) {
    asm volatile(
        "mma.sync.aligned.m16n8k16.row.col.f32.bf16.bf16.f32 "
        "{%0,%1,%2,%3},{%4,%5,%6,%7},{%8,%9},{%0,%1,%2,%3};"
        : "+f"(d[0]), "+f"(d[1]), "+f"(d[2]), "+f"(d[3])
        : "r"(a[0]), "r"(a[1]), "r"(a[2]), "r"(a[3]), "r"(b0), "r"(b1));
}
__device__ __forceinline__ void mma_f16(float* d, const uint32_t* a, uint32_t b0, uint32_t b1) {
    asm volatile(
        "mma.sync.aligned.m16n8k16.row.col.f32.f16.f16.f32 "
        "{%0,%1,%2,%3},{%4,%5,%6,%7},{%8,%9},{%0,%1,%2,%3};"
        : "+f"(d[0]), "+f"(d[1]), "+f"(d[2]), "+f"(d[3])
        : "r"(a[0]), "r"(a[1]), "r"(a[2]), "r"(a[3]), "r"(b0), "r"(b1));
}
__device__ __forceinline__ uint32_t pack_hilo_bf16(float f) {
    __nv_bfloat16 h = __float2bfloat16(f);
    float fh = __bfloat162float(h);
    __nv_bfloat16 l = __float2bfloat16(f - fh);
    return ((uint32_t)__bfloat16_as_ushort(l) << 16) | (uint32_t)__bfloat16_as_ushort(h);
}
__device__ __forceinline__ uint32_t pack_hilo_f16(float f) {
    __half h = __float2half_rn(f);
    float fh = __half2float(h);
    __half l = __float2half_rn(f - fh);
    return ((uint32_t)__half_as_ushort(l) << 16) | (uint32_t)__half_as_ushort(h);
}
#define CP_ASYNC16(dst, src) \
    asm volatile("cp.async.cg.shared.global [%0], [%1], 16;" :: "r"(dst), "l"(src) : "memory")
#define CP_COMMIT() asm volatile("cp.async.commit_group;" ::: "memory")
#define CP_WAIT1()  asm volatile("cp.async.wait_group 1;" ::: "memory")

// ===== init =====
__global__ void k_init() {
    int i = blockIdx.x * blockDim.x + threadIdx.x;
    if (i < 81 * 81) d_F[i] = 0.f;
    if (i < 3) d_acc[i] = 0.0;
}

// ===== repack weight: d_wt (f32) + d_Ab (bf16 hi/lo) =====
__global__ void k_repack(const float* __restrict__ w) {
    int idx = blockIdx.x * blockDim.x + threadIdx.x;
    if (idx >= 256 * 2304) return;
    int p = idx / 2304;
    int r = idx - p * 2304;
    int c = r / 9, t = r - c * 9;
    float v = w[idx];
    d_wt[(t * 256 + c) * 256 + p] = v;
    d_Ab[(t * 256 + c) * 256 + p] = pack_hilo_bf16(v);
}

// ===== build d_xt: padded [b][hr34][hc34][ci256] packed fp16 hi/lo =====
__global__ void k_xt(const float* __restrict__ x) {
    __shared__ uint32_t s[34][256];
    int hr = blockIdx.x;     // 0..33
    int b  = blockIdx.y;     // 0..31
    int tid = threadIdx.x;
    int hsrc = (hr + 31) & 31;
    for (int idx = tid; idx < 8192; idx += 256) {
        int ci = idx >> 5, w = idx & 31;
        float f = x[(((size_t)b * 256 + ci) * 32 + hsrc) * 32 + w];
        s[w + 1][ci] = pack_hilo_f16(f);
    }
    __syncthreads();
    if (tid < 256) { s[0][tid] = s[32][tid]; s[33][tid] = s[1][tid]; }
    __syncthreads();
    for (int idx = tid; idx < 34 * 256; idx += 256) {
        int hc = idx >> 8, ci = idx & 255;
        d_xt[(((size_t)b * 34 + hr) * 34 + hc) * 256 + ci] = s[hc][ci];
    }
}

// ===== pack W stages: s=chunk*9+tap : [co 256][stride 20] u32, fp16 ci pairs =====
__global__ void k_wB2(const float* __restrict__ w) {
    int idx = blockIdx.x * 256 + threadIdx.x;
    if (idx >= 72 * 4096) return;
    int s = idx >> 12;
    int r = idx & 4095;
    int co = r >> 4, ci2 = r & 15;
    int chunk = s / 9, tap = s - chunk * 9;
    float v0 = w[(co * 256 + chunk * 32 + ci2 * 2 + 0) * 9 + tap];
    float v1 = w[(co * 256 + chunk * 32 + ci2 * 2 + 1) * 9 + tap];
    uint32_t h0 = (uint32_t)__half_as_ushort(__float2half_rn(v0));
    uint32_t h1 = (uint32_t)__half_as_ushort(__float2half_rn(v1));
    d_wB2[(size_t)s * 5120 + co * 20 + ci2] = (h1 << 16) | h0;
}

// ===== fp16 2-product mma conv =====
// grid (32 b, 8 rowblock), 256 threads (8 warps: 2 M x 4 N)
#define HALO_STRIDE 36
#define OFF_RING   29376                 // 204*36*4
#define RING_U32   5120                  // 256*20
#define RING_BYTES 20480
#define OFF_BIAS   132096                // after epi region 256*129*4
#define SMEM_BYTES 133120

__global__ __launch_bounds__(256, 1)
void k_conv_mma(const float* __restrict__ bias, float* __restrict__ y) {
    extern __shared__ uint32_t sm[];
    uint32_t* sHalo = sm;                              // [204][36]
    uint32_t* sRing = sm + OFF_RING / 4;               // 3 x [256][20]
    float*    sEpi  = (float*)sm;                      // [256][129] reuse
    float*    sBias = (float*)(sm + OFF_BIAS / 4);
    uint32_t sbase;
    asm("{ .reg .u64 t; cvta.to.shared.u64 t, %1; cvt.u32.u64 %0, t; }"
        : "=r"(sbase) : "l"((void*)sm));

    int tid  = threadIdx.x;
    int lane = tid & 31, warp = tid >> 5;
    int wm = warp >> 2, wn = warp & 3;     // 2 x 4
    int b = blockIdx.x, r0 = blockIdx.y * 4;

    sBias[tid] = bias[tid];

    float acc[4][8][4];
#pragma unroll
    for (int i = 0; i < 4; i++)
#pragma unroll
        for (int j = 0; j < 8; j++)
#pragma unroll
            for (int q = 0; q < 4; q++) acc[i][j][q] = 0.f;

    // prologue: W stages 0, 1
#pragma unroll
    for (int s0 = 0; s0 < 2; s0++) {
        const char* src = (const char*)d_wB2 + (size_t)s0 * RING_BYTES;
        uint32_t dst = sbase + OFF_RING + (uint32_t)s0 * RING_BYTES;
#pragma unroll
        for (int q = 0; q < 5; q++) {
            int off = (q * 256 + tid) * 16;
            CP_ASYNC16(dst + off, src + off);
        }
        CP_COMMIT();
    }

    int lr = lane >> 2;         // 0..7
    int lk = (lane & 3) * 2;    // 0,2,4,6

#pragma unroll 1
    for (int s = 0; s < 72; s++) {
        int chunk = s / 9;
        int tap = s - chunk * 9;
        int ta = tap / 3, tb = tap - ta * 3;

        if (tap == 0) {
            __syncthreads();     // old halo no longer read
            int ci0 = chunk * 32;
            for (int f = tid; f < 6528; f += 256) {
                int seg = f >> 5, ci = f & 31;
                int hr = seg / 34, hc = seg - hr * 34;
                sHalo[seg * HALO_STRIDE + ci] =
                    d_xt[(((size_t)b * 34 + r0 + hr) * 34 + hc) * 256 + ci0 + ci];
            }
        }

        CP_WAIT1();
        __syncthreads();

        // prefetch stage s+2
        if (s + 2 < 72) {
            const char* src = (const char*)d_wB2 + (size_t)(s + 2) * RING_BYTES;
            uint32_t dst = sbase + OFF_RING + (uint32_t)((s + 2) % 3) * RING_BYTES;
#pragma unroll
            for (int q = 0; q < 5; q++) {
                int off = (q * 256 + tid) * 16;
                CP_ASYNC16(dst + off, src + off);
            }
        }
        CP_COMMIT();

        const uint32_t* Bp = sRing + (s % 3) * RING_U32;

        int segb[4];
#pragma unroll
        for (int mf = 0; mf < 4; mf++) {
            int m0 = wm * 64 + mf * 16 + lr;
            int pr = m0 >> 5, pc = m0 & 31;
            segb[mf] = ((pr + ta) * 34 + pc + tb) * HALO_STRIDE;
        }

#pragma unroll
        for (int k2 = 0; k2 < 32; k2 += 16) {
            int kb = k2 + lk;
            uint32_t Ah[4][4], Al[4][4];
#pragma unroll
            for (int mf = 0; mf < 4; mf++) {
                const uint32_t* base = sHalo + segb[mf] + kb;
                uint2 u00 = *(const uint2*)(base);
                uint2 u10 = *(const uint2*)(base + 8 * HALO_STRIDE);
                uint2 u01 = *(const uint2*)(base + 8);
                uint2 u11 = *(const uint2*)(base + 8 * HALO_STRIDE + 8);
                Ah[mf][0] = prmt32(u00.x, u00.y, 0x5410); Al[mf][0] = prmt32(u00.x, u00.y, 0x7632);
                Ah[mf][1] = prmt32(u10.x, u10.y, 0x5410); Al[mf][1] = prmt32(u10.x, u10.y, 0x7632);
                Ah[mf][2] = prmt32(u01.x, u01.y, 0x5410); Al[mf][2] = prmt32(u01.x, u01.y, 0x7632);
                Ah[mf][3] = prmt32(u11.x, u11.y, 0x5410); Al[mf][3] = prmt32(u11.x, u11.y, 0x7632);
            }
#pragma unroll
            for (int nf = 0; nf < 8; nf++) {
                int co = wn * 64 + nf * 8 + lr;
                const uint32_t* bb = Bp + co * 20 + (k2 >> 1) + (lk >> 1);
                uint32_t b0 = bb[0];
                uint32_t b1 = bb[4];
#pragma unroll
                for (int mf = 0; mf < 4; mf++) {
                    mma_f16(acc[mf][nf], Ah[mf], b0, b1);   // xh*wh
                    mma_f16(acc[mf][nf], Al[mf], b0, b1);   // xl*wh
                }
            }
        }
    }

    // epilogue: transpose through smem, add bias, coalesced store
    __syncthreads();
#pragma unroll
    for (int mf = 0; mf < 4; mf++)
#pragma unroll
        for (int nf = 0; nf < 8; nf++) {
            int m0 = wm * 64 + mf * 16 + lr;
            int co = wn * 64 + nf * 8 + lk;
            sEpi[(co + 0) * 129 + m0]     = acc[mf][nf][0];
            sEpi[(co + 1) * 129 + m0]     = acc[mf][nf][1];
            sEpi[(co + 0) * 129 + m0 + 8] = acc[mf][nf][2];
            sEpi[(co + 1) * 129 + m0 + 8] = acc[mf][nf][3];
        }
    __syncthreads();
    for (int idx = tid; idx < 32768; idx += 256) {
        int co = idx >> 7, m = idx & 127;
        float v = sEpi[co * 129 + m] + sBias[co];
        int i = r0 + (m >> 5), j = m & 31;
        y[(((size_t)b * 256 + co) * 32 + i) * 32 + j] = v;
    }
}

// ===== Nb = A A^T via bf16 3-product MMA; A = d_Ab [2304][256] =====
// grid (18, 18), tile 128x128, K=256 in 8 chunks of 32
#define NB_TILE_U32 4608    // 128 * 36
#define NB_SMEM (4 * NB_TILE_U32 * 4)   // 73728 B

__global__ __launch_bounds__(256, 1) void k_nbm() {
    extern __shared__ uint32_t nsm[];
    uint32_t* As = nsm;                       // 2 bufs
    uint32_t* Bs = nsm + 2 * NB_TILE_U32;     // 2 bufs
    uint32_t sbase;
    asm("{ .reg .u64 t; cvta.to.shared.u64 t, %1; cvt.u32.u64 %0, t; }"
        : "=r"(sbase) : "l"((void*)nsm));
    int tid = threadIdx.x, lane = tid & 31, warp = tid >> 5;
    int wm = warp >> 2, wn = warp & 3;
    int rt = blockIdx.y * 128, ct = blockIdx.x * 128;
    int lr = lane >> 2, lk = (lane & 3) * 2;

    float acc[4][4][4];
#pragma unroll
    for (int i = 0; i < 4; i++)
#pragma unroll
        for (int j = 0; j < 4; j++)
#pragma unroll
            for (int q = 0; q < 4; q++) acc[i][j][q] = 0.f;

#define NB_ISSUE(buf, chunk) do { \
    _Pragma("unroll") \
    for (int it = 0; it < 4; it++) { \
        int idx = it * 256 + tid; \
        int row = idx >> 3, q = idx & 7; \
        uint32_t dA = sbase + ((buf) * NB_TILE_U32 + row * 36 + q * 4) * 4; \
        const char* sA = (const char*)d_Ab + (((size_t)(rt + row)) * 256 + (chunk) * 32 + q * 4) * 4; \
        CP_ASYNC16(dA, sA); \
        uint32_t dB = sbase + ((2 + (buf)) * NB_TILE_U32 + row * 36 + q * 4) * 4; \
        const char* sB = (const char*)d_Ab + (((size_t)(ct + row)) * 256 + (chunk) * 32 + q * 4) * 4; \
        CP_ASYNC16(dB, sB); \
    } } while (0)

    NB_ISSUE(0, 0);
    CP_COMMIT();
#pragma unroll 1
    for (int chunk = 0; chunk < 8; chunk++) {
        if (chunk + 1 < 8) NB_ISSUE((chunk + 1) & 1, chunk + 1);
        CP_COMMIT();
        CP_WAIT1();
        __syncthreads();
        const uint32_t* Ab = As + (chunk & 1) * NB_TILE_U32;
        const uint32_t* Bb = Bs + (chunk & 1) * NB_TILE_U32;
#pragma unroll
        for (int ks = 0; ks < 2; ks++) {
            int kb = ks * 16 + lk;
            uint32_t Ah[4][4], Al[4][4];
#pragma unroll
            for (int mf = 0; mf < 4; mf++) {
                int m = wm * 64 + mf * 16 + lr;
                uint2 u00 = *(const uint2*)(Ab + m * 36 + kb);
                uint2 u10 = *(const uint2*)(Ab + (m + 8) * 36 + kb);
                uint2 u01 = *(const uint2*)(Ab + m * 36 + kb + 8);
                uint2 u11 = *(const uint2*)(Ab + (m + 8) * 36 + kb + 8);
                Ah[mf][0] = prmt32(u00.x, u00.y, 0x5410); Al[mf][0] = prmt32(u00.x, u00.y, 0x7632);
                Ah[mf][1] = prmt32(u10.x, u10.y, 0x5410); Al[mf][1] = prmt32(u10.x, u10.y, 0x7632);
                Ah[mf][2] = prmt32(u01.x, u01.y, 0x5410); Al[mf][2] = prmt32(u01.x, u01.y, 0x7632);
                Ah[mf][3] = prmt32(u11.x, u11.y, 0x5410); Al[mf][3] = prmt32(u11.x, u11.y, 0x7632);
            }
#pragma unroll
            for (int nf = 0; nf < 4; nf++) {
                int n = wn * 32 + nf * 8 + lr;
                uint2 v0 = *(const uint2*)(Bb + n * 36 + kb);
                uint2 v1 = *(const uint2*)(Bb + n * 36 + kb + 8);
                uint32_t Bh0 = prmt32(v0.x, v0.y, 0x5410), Bl0 = prmt32(v0.x, v0.y, 0x7632);
                uint32_t Bh1 = prmt32(v1.x, v1.y, 0x5410), Bl1 = prmt32(v1.x, v1.y, 0x7632);
#pragma unroll
                for (int mf = 0; mf < 4; mf++) {
                    mma_bf16(acc[mf][nf], Ah[mf], Bh0, Bh1);
                    mma_bf16(acc[mf][nf], Ah[mf], Bl0, Bl1);
                    mma_bf16(acc[mf][nf], Al[mf], Bh0, Bh1);
                }
            }
        }
        __syncthreads();
    }

#pragma unroll
    for (int mf = 0; mf < 4; mf++)
#pragma unroll
        for (int nf = 0; nf < 4; nf++) {
            int m = rt + wm * 64 + mf * 16 + lr;
            int n = ct + wn * 32 + nf * 8 + lk;
            float2 lo = make_float2(acc[mf][nf][0], acc[mf][nf][1]);
            float2 hi = make_float2(acc[mf][nf][2], acc[mf][nf][3]);
            *(float2*)&d_Nb[(size_t)m * NB_DIM + n] = lo;
            *(float2*)&d_Nb[(size_t)(m + 8) * NB_DIM + n] = hi;
        }
}

// ===== S[t*9+t'][p] = sum_c w_t[p,c] w_t'[p,c] =====
__global__ void k_S(const float* __restrict__ w) {
    __shared__ float sh[81];
    int p = blockIdx.x, tid = threadIdx.x;
    if (tid < 81) sh[tid] = 0.f;
    __syncthreads();
    float wv[9];
#pragma unroll
    for (int t = 0; t < 9; t++) wv[t] = w[(p * 256 + tid) * 9 + t];
#pragma unroll
    for (int t = 0; t < 9; t++)
#pragma unroll
        for (int t2 = t; t2 < 9; t2++) {
            float pr = wv[t] * wv[t2];
#pragma unroll
            for (int o = 16; o; o >>= 1) pr += __shfl_xor_sync(0xffffffffu, pr, o);
            if ((tid & 31) == 0) atomicAdd(&sh[t * 9 + t2], pr);
        }
    __syncthreads();
    if (tid < 81) {
        int t = tid / 9, t2 = tid - t * 9;
        d_S[tid * 256 + p] = (t2 >= t) ? sh[t * 9 + t2] : sh[t2 * 9 + t];
    }
}

// ===== T[t*9+t'][c] = sum_p w_t[p,c] w_t'[p,c] =====
__global__ void k_T() {
    __shared__ float sh[81];
    int c = blockIdx.x, tid = threadIdx.x;
    if (tid < 81) sh[tid] = 0.f;
    __syncthreads();
    float wv[9];
#pragma unroll
    for (int t = 0; t < 9; t++) wv[t] = d_wt[(t * 256 + c) * 256 + tid];
#pragma unroll
    for (int t = 0; t < 9; t++)
#pragma unroll
        for (int t2 = t; t2 < 9; t2++) {
            float pr = wv[t] * wv[t2];
#pragma unroll
            for (int o = 16; o; o >>= 1) pr += __shfl_xor_sync(0xffffffffu, pr, o);
            if ((tid & 31) == 0) atomicAdd(&sh[t * 9 + t2], pr);
        }
    __syncthreads();
    if (tid < 81) {
        int t = tid / 9, t2 = tid - t * 9;
        d_T[tid * 256 + c] = (t2 >= t) ? sh[t * 9 + t2] : sh[t2 * 9 + t];
    }
}

// ===== per-bin row/col norms + diag^2 =====
__global__ void k_rowcol() {
    __shared__ float cosv[81];
    __shared__ double red[3][8];
    int bin = blockIdx.x;
    int u = bin / 17, v = bin - u * 17;
    int tid = threadIdx.x;
    if (tid < 81) {
        int t = tid / 9, t2 = tid - t * 9;
        int da = t / 3 - t2 / 3;
        int db = (t % 3) - (t2 % 3);
        cosv[tid] = cospif((float)(u * da + v * db) / 16.0f);
    }
    __syncthreads();
    float rn2 = 0.f, cn2 = 0.f;
#pragma unroll
    for (int q = 0; q < 81; q++) {
        float cq = cosv[q];
        rn2 += cq * d_S[q * 256 + tid];
        cn2 += cq * d_T[q * 256 + tid];
    }
    float rdev = sqrtf(fmaxf(rn2, 0.f)) - 1.f;
    float cdev = sqrtf(fmaxf(cn2, 0.f)) - 1.f;
    double v0 = (double)rdev * (double)rdev;
    double v1 = (double)cdev * (double)cdev;
    double v2 = (double)rn2 * (double)rn2;
#pragma unroll
    for (int o = 16; o; o >>= 1) {
        v0 += __shfl_xor_sync(0xffffffffu, v0, o);
        v1 += __shfl_xor_sync(0xffffffffu, v1, o);
        v2 += __shfl_xor_sync(0xffffffffu, v2, o);
    }
    int wid = tid >> 5, lane = tid & 31;
    if (lane == 0) { red[0][wid] = v0; red[1][wid] = v1; red[2][wid] = v2; }
    __syncthreads();
    if (tid == 0) {
        double s0 = 0, s1 = 0, s2 = 0;
        for (int i = 0; i < 8; i++) { s0 += red[0][i]; s1 += red[1][i]; s2 += red[2][i]; }
        atomicAdd(&d_acc[0], s0);
        atomicAdd(&d_acc[1], s1);
        atomicAdd(&d_acc[2], s2);
    }
}

// ===== F = Frobenius products of Nb blocks (split-K) =====
__global__ __launch_bounds__(256) void k_F() {
    __shared__ float Vb[81][65];
    int tid = threadIdx.x;
    int t1 = tid, t2 = tid + 256;
    float a1[16], a2[16];
#pragma unroll
    for (int q = 0; q < 16; q++) { a1[q] = 0.f; a2[q] = 0.f; }
    int i1 = (t1 / 21) * 4, j1 = (t1 % 21) * 4;
    int i2 = (t2 / 21) * 4, j2 = (t2 % 21) * 4;

    for (int chunk = blockIdx.x; chunk < 1024; chunk += gridDim.x) {
        __syncthreads();
        int k0  = chunk * 64;
        int c   = k0 >> 8;
        int cp0 = k0 & 255;
        for (int idx = tid; idx < 81 * 64; idx += 256) {
            int r = idx >> 6, kk = idx & 63;
            int uu = r / 9, vv = r - uu * 9;
            Vb[r][kk] = d_Nb[(size_t)(uu * 256 + c) * NB_DIM + vv * 256 + cp0 + kk];
        }
        __syncthreads();
        for (int kk = 0; kk < 64; kk++) {
            float av[4], bv[4];
#pragma unroll
            for (int q = 0; q < 4; q++) {
                av[q] = (i1 + q < 81) ? Vb[i1 + q][kk] : 0.f;
                bv[q] = (j1 + q < 81) ? Vb[j1 + q][kk] : 0.f;
            }
#pragma unroll
            for (int qi = 0; qi < 4; qi++)
#pragma unroll
                for (int qj = 0; qj < 4; qj++) a1[qi * 4 + qj] += av[qi] * bv[qj];
            if (t2 < 441) {
#pragma unroll
                for (int q = 0; q < 4; q++) {
                    av[q] = (i2 + q < 81) ? Vb[i2 + q][kk] : 0.f;
                    bv[q] = (j2 + q < 81) ? Vb[j2 + q][kk] : 0.f;
                }
#pragma unroll
                for (int qi = 0; qi < 4; qi++)
#pragma unroll
                    for (int qj = 0; qj < 4; qj++) a2[qi * 4 + qj] += av[qi] * bv[qj];
            }
        }
    }
#pragma unroll
    for (int qi = 0; qi < 4; qi++)
#pragma unroll
        for (int qj = 0; qj < 4; qj++) {
            if (i1 + qi < 81 && j1 + qj < 81) atomicAdd(&d_F[(i1 + qi) * 81 + j1 + qj], a1[qi * 4 + qj]);
            if (t2 < 441 && i2 + qi < 81 && j2 + qj < 81) atomicAdd(&d_F[(i2 + qi) * 81 + j2 + qj], a2[qi * 4 + qj]);
        }
}

// ===== final: assemble L =====
__global__ void k_final(float* __restrict__ out, long long lpos) {
    __shared__ double Vt[5];
    __shared__ double red[8];
    int tid = threadIdx.x;
    if (tid < 5) {
        double s = 0.0;
        for (int v = 0; v <= 16; v++) s += cos(M_PI * (double)tid * (double)v / 16.0);
        Vt[tid] = s;
    }
    __syncthreads();
    double tf = 0.0;
    for (int idx = tid; idx < 6561; idx += blockDim.x) {
        int t  = idx / 729;
        int tp = (idx / 81) % 9;
        int s  = (idx / 9) % 9;
        int sp = idx % 9;
        if ((t / 3 - tp / 3) != (s / 3 - sp / 3)) continue;
        int db = ((t % 3) - (tp % 3)) - ((s % 3) - (sp % 3));
        if (db < 0) db = -db;
        tf += 32.0 * Vt[db] * (double)d_F[(t * 9 + s) * 81 + (tp * 9 + sp)];
    }
#pragma unroll
    for (int o = 16; o; o >>= 1) tf += __shfl_xor_sync(0xffffffffu, tf, o);
    if ((tid & 31) == 0) red[tid >> 5] = tf;
    __syncthreads();
    if (tid == 0) {
        double total = 0.0;
        for (int i = 0; i < 8; i++) total += red[i];
        double count   = 544.0 * (256.0 * 255.0 * 0.5);
        double Ang     = (total - d_acc[2]) * 0.5 / count;
        double RowLoss = d_acc[0] / (544.0 * 256.0);
        double ColLoss = d_acc[1] / (544.0 * 256.0);
        double L = 256.0 * ColLoss + 256.0 * RowLoss + Ang;
        if (lpos >= 0) out[lpos] = (float)L;
    }
}

extern "C" void kernel_launch(void* const* d_in, const int* in_sizes, int n_in,
                              void* d_out, int out_size) {
    const float* x    = (const float*)d_in[0];
    const float* w    = (const float*)d_in[1];
    const float* bias = (const float*)d_in[2];
    float* out = (float*)d_out;

    cudaFuncSetAttribute(k_conv_mma, cudaFuncAttributeMaxDynamicSharedMemorySize, SMEM_BYTES);
    cudaFuncSetAttribute(k_nbm, cudaFuncAttributeMaxDynamicSharedMemorySize, NB_SMEM);

    k_init<<<26, 256>>>();
    k_repack<<<(256 * 2304 + 255) / 256, 256>>>(w);
    k_xt<<<dim3(34, 32), 256>>>(x);
    k_wB2<<<1152, 256>>>(w);
    k_conv_mma<<<dim3(32, 8), 256, SMEM_BYTES>>>(bias, out);
    k_S<<<256, 256>>>(w);
    k_T<<<256, 256>>>();
    k_rowcol<<<544, 256>>>();
    k_nbm<<<dim3(18, 18), 256, NB_SMEM>>>();
    k_F<<<256, 256>>>();
    long long lpos = (out_size > Y_ELEMS) ? (long long)out_size - 1 : -1;
    k_final<<<1, 256>>>(out, lpos);
    (void)in_sizes; (void)n_in;
}